// round 13
// baseline (speedup 1.0000x reference)
#include <cuda_runtime.h>
#include <cuda_fp16.h>
#include <cstdint>

// Problem constants
#define B_    2
#define S_    512
#define D_    512
#define MTOK  1024          // B*S tokens
#define NTOT  1536          // w1 | w2 | w3
#define EPS_  1e-5f

// Static device scratch
__device__ float  g_P[MTOK * NTOT];     // w2|w3 projections (w1 region unused)
__device__ float4 g_W1R[MTOK][16];      // per-token partials: sum,sq,dot,sx

// Column permutation: every 48-block = [32 w13-cols][16 w2-cols].
// Original concat: w1=[0,512) w2=[512,1024) w3=[1024,1536).
__device__ __forceinline__ int perm_to_orig(int p) {
    const int b = p / 48, r = p % 48;
    if (r < 32) { const int u = b * 32 + r; return (u < 512) ? u : u + 512; }
    return 512 + b * 16 + (r - 32);
}

// ---------------------------------------------------------------------------
// Fused GEMM: loads fp32 X/W, converts to fp16 hi/lo in-kernel, mixed
// pass-count MMA, fused w1 reduction. BM=128 BN=96 BK=32, grid 8x16.
// ---------------------------------------------------------------------------
#define BM 128
#define BN 96
#define BK 32
#define KP 40
#define A_OFF   0
#define A1_OFF  (BM * KP)                    // 5120
#define B_OFF   (2 * BM * KP)                // 10240
#define B1_OFF  (2 * BM * KP + BN * KP)      // 14080 (compact: 32 rows)
#define STAGE_H (2 * BM * KP + BN * KP + 32 * KP)  // 15360 halves
#define NSTG    2
#define GSMEM   (NSTG * STAGE_H * 2)               // 61440 B

__device__ __forceinline__ void ldsm_x4(uint32_t* r, uint32_t addr) {
    asm volatile("ldmatrix.sync.aligned.m8n8.x4.shared.b16 {%0,%1,%2,%3}, [%4];"
        : "=r"(r[0]), "=r"(r[1]), "=r"(r[2]), "=r"(r[3]) : "r"(addr));
}

__device__ __forceinline__ void mma_f16(float* c,
    uint32_t a0, uint32_t a1, uint32_t a2, uint32_t a3,
    uint32_t b0, uint32_t b1)
{
    asm volatile(
        "mma.sync.aligned.m16n8k16.row.col.f32.f16.f16.f32 "
        "{%0,%1,%2,%3}, {%4,%5,%6,%7}, {%8,%9}, {%0,%1,%2,%3};"
        : "+f"(c[0]), "+f"(c[1]), "+f"(c[2]), "+f"(c[3])
        : "r"(a0), "r"(a1), "r"(a2), "r"(a3), "r"(b0), "r"(b1));
}

// Convert 4 fp32 -> packed hi (uint2) and lo (uint2) fp16 pairs.
__device__ __forceinline__ void cvt_hilo(float4 v, uint2& H, uint2& L) {
    __half h0 = __float2half_rn(v.x), h1 = __float2half_rn(v.y);
    __half h2 = __float2half_rn(v.z), h3 = __float2half_rn(v.w);
    __half l0 = __float2half_rn(v.x - __half2float(h0));
    __half l1 = __float2half_rn(v.y - __half2float(h1));
    __half l2 = __float2half_rn(v.z - __half2float(h2));
    __half l3 = __float2half_rn(v.w - __half2float(h3));
    __half2 hp0 = __halves2half2(h0, h1), hp1 = __halves2half2(h2, h3);
    __half2 lp0 = __halves2half2(l0, l1), lp1 = __halves2half2(l2, l3);
    H.x = *(uint32_t*)&hp0;  H.y = *(uint32_t*)&hp1;
    L.x = *(uint32_t*)&lp0;  L.y = *(uint32_t*)&lp1;
}
__device__ __forceinline__ uint2 cvt_hi(float4 v) {
    __half h0 = __float2half_rn(v.x), h1 = __float2half_rn(v.y);
    __half h2 = __float2half_rn(v.z), h3 = __float2half_rn(v.w);
    __half2 hp0 = __halves2half2(h0, h1), hp1 = __halves2half2(h2, h3);
    uint2 H; H.x = *(uint32_t*)&hp0;  H.y = *(uint32_t*)&hp1;
    return H;
}

__global__ __launch_bounds__(256, 1) void gemm3_fused(
    const float* __restrict__ X,
    const float* __restrict__ Win,
    const float* __restrict__ Wout,
    const float* __restrict__ Wb)
{
    extern __shared__ __half sm[];

    const int tid   = threadIdx.x;
    const int lane  = tid & 31;
    const int wid   = tid >> 5;
    const int warpM = wid >> 1;         // 0..3
    const int warpN = wid & 1;          // 0..1
    const int gID   = lane >> 2;        // 0..7
    const int tIG   = lane & 3;         // 0..3
    const int m0    = blockIdx.x * BM;
    const int by    = blockIdx.y;
    const int n0    = by * BN;          // permuted col base

    const uint32_t sbase = (uint32_t)__cvta_generic_to_shared(sm);

    // ---- per-thread load geometry (fixed across tiles) ----
    // A: 128 rows x 8 quads = 1024 float4, 4 per thread.
    //    thread t: row = t>>1, colbase = (t&1)*16, quads j*4.
    const int raw  = tid >> 1;
    const int caw  = (tid & 1) * 16;
    const float* pA = X + (m0 + raw) * D_ + caw;
    const int sA0o = A_OFF  + raw * KP + caw;     // halves, + stage offset
    const int sA1o = A1_OFF + raw * KP + caw;

    // B: 96 rows x 8 quads = 768 float4, 3 per thread (qid = tid + 256*i).
    const float* pB[3];
    int sBo[3], sBlo[3];
    bool isW2[3];
    #pragma unroll
    for (int i = 0; i < 3; ++i) {
        const int qid = tid + 256 * i;
        const int rb  = qid >> 3;
        const int cb  = (qid & 7) * 4;
        const int o   = perm_to_orig(n0 + rb);
        const float* W = (o < D_) ? Win + o * D_
                       : (o < 2 * D_) ? Wout + (o - D_) * D_
                                      : Wb + (o - 2 * D_) * D_;
        pB[i]  = W + cb;
        sBo[i] = B_OFF + rb * KP + cb;
        const int r48 = rb % 48;
        isW2[i] = (r48 >= 32);
        sBlo[i] = B1_OFF + ((rb / 48) * 16 + (r48 - 32)) * KP + cb;
    }

    // ldmatrix per-thread address components (within a stage, in halves)
    const int rA  = warpM * 32 + (lane & 15);
    const int cA  = (lane >> 4) * 8;
    const int tB  = lane >> 3;
    const int rBh = warpN * 48 + (tB >> 1) * 8 + (lane & 7);
    const int rBl = warpN * 16 + (tB >> 1) * 8 + (lane & 7);
    const int cB  = (tB & 1) * 8;

    float acc[2][6][4];
    #pragma unroll
    for (int i = 0; i < 2; i++)
        #pragma unroll
        for (int j = 0; j < 6; j++)
            #pragma unroll
            for (int q = 0; q < 4; q++) acc[i][j][q] = 0.f;

    float4 bufA[4], bufB[3];

    auto ldg_tile = [&](int t) {
        const int k0 = t * BK;
        #pragma unroll
        for (int j = 0; j < 4; ++j)
            bufA[j] = *reinterpret_cast<const float4*>(pA + k0 + 4 * j);
        #pragma unroll
        for (int i = 0; i < 3; ++i)
            bufB[i] = *reinterpret_cast<const float4*>(pB[i] + k0);
    };

    auto sts_convert = [&](int stg) {
        __half* s = sm + stg * STAGE_H;
        #pragma unroll
        for (int j = 0; j < 4; ++j) {
            uint2 H, L;
            cvt_hilo(bufA[j], H, L);
            *reinterpret_cast<uint2*>(&s[sA0o + 4 * j]) = H;
            *reinterpret_cast<uint2*>(&s[sA1o + 4 * j]) = L;
        }
        #pragma unroll
        for (int i = 0; i < 3; ++i) {
            if (isW2[i]) {
                uint2 H, L;
                cvt_hilo(bufB[i], H, L);
                *reinterpret_cast<uint2*>(&s[sBo[i]])  = H;
                *reinterpret_cast<uint2*>(&s[sBlo[i]]) = L;
            } else {
                *reinterpret_cast<uint2*>(&s[sBo[i]]) = cvt_hi(bufB[i]);
            }
        }
    };

    auto compute = [&](int stg) {
        const uint32_t sst = sbase + (uint32_t)(stg * STAGE_H) * 2u;
        const uint32_t aA0 = sst + (uint32_t)(A_OFF  + rA * KP + cA) * 2u;
        const uint32_t aA1 = sst + (uint32_t)(A1_OFF + rA * KP + cA) * 2u;
        const uint32_t aBh = sst + (uint32_t)(B_OFF  + rBh * KP + cB) * 2u;
        const uint32_t aBl = sst + (uint32_t)(B1_OFF + rBl * KP + cB) * 2u;
        #pragma unroll
        for (int kk = 0; kk < BK; kk += 16) {
            const uint32_t ko = (uint32_t)(kk * 2);
            uint32_t ah[2][4], al[2][4], bh[6][2], bl[2][2];
            ldsm_x4(ah[0], aA0 + ko);
            ldsm_x4(ah[1], aA0 + ko + (uint32_t)(16 * KP * 2));
            ldsm_x4(al[0], aA1 + ko);
            ldsm_x4(al[1], aA1 + ko + (uint32_t)(16 * KP * 2));
            #pragma unroll
            for (int p = 0; p < 3; ++p) {
                uint32_t r[4];
                ldsm_x4(r, aBh + ko + (uint32_t)(p * 16 * KP * 2));
                bh[2 * p][0] = r[0];  bh[2 * p][1] = r[1];
                bh[2 * p + 1][0] = r[2];  bh[2 * p + 1][1] = r[3];
            }
            {
                uint32_t r[4];
                ldsm_x4(r, aBl + ko);
                bl[0][0] = r[0];  bl[0][1] = r[1];
                bl[1][0] = r[2];  bl[1][1] = r[3];
            }
            // w2 atoms: 3-pass exact
            #pragma unroll
            for (int i = 0; i < 2; ++i)
                #pragma unroll
                for (int jj = 0; jj < 2; ++jj)
                    mma_f16(acc[i][4 + jj], ah[i][0], ah[i][1], ah[i][2], ah[i][3],
                            bl[jj][0], bl[jj][1]);
            #pragma unroll
            for (int i = 0; i < 2; ++i)
                #pragma unroll
                for (int jj = 0; jj < 2; ++jj)
                    mma_f16(acc[i][4 + jj], al[i][0], al[i][1], al[i][2], al[i][3],
                            bh[4 + jj][0], bh[4 + jj][1]);
            // all atoms: ah*bh
            #pragma unroll
            for (int i = 0; i < 2; ++i)
                #pragma unroll
                for (int j = 0; j < 6; ++j)
                    mma_f16(acc[i][j], ah[i][0], ah[i][1], ah[i][2], ah[i][3],
                            bh[j][0], bh[j][1]);
        }
    };

    constexpr int T = D_ / BK;   // 16
    ldg_tile(0);
    #pragma unroll 1
    for (int t = 0; t < T; ++t) {
        __syncthreads();                 // stage (t&1) consumers (t-2) done
        sts_convert(t & 1);
        if (t + 1 < T) ldg_tile(t + 1);  // latency hidden under compute(t)
        __syncthreads();                 // stores visible
        compute(t & 1);
    }

    // -------- Epilogue --------
    if (by < 8) {
        // w13 atoms are w1 columns: reduce in-register, write partials.
        const int ub = (2 * by + warpN) * 32;       // orig col base (32 cols)
        #pragma unroll
        for (int i = 0; i < 2; ++i)
            #pragma unroll
            for (int half = 0; half < 2; ++half) {
                const int row = m0 + warpM * 32 + i * 16 + half * 8 + gID;
                float s = 0.f, qd = 0.f, dx = 0.f, sx = 0.f;
                #pragma unroll
                for (int j = 0; j < 4; ++j) {
                    const float w1a = acc[i][j][half * 2 + 0];
                    const float w1b = acc[i][j][half * 2 + 1];
                    const float2 xv = *reinterpret_cast<const float2*>(
                        &X[row * D_ + ub + j * 8 + 2 * tIG]);
                    s  += w1a + w1b;
                    qd += w1a * w1a + w1b * w1b;
                    dx += w1a * xv.x + w1b * xv.y;
                    sx += xv.x + xv.y;
                }
                #pragma unroll
                for (int o = 1; o < 4; o <<= 1) {
                    s  += __shfl_xor_sync(0xffffffffu, s,  o);
                    qd += __shfl_xor_sync(0xffffffffu, qd, o);
                    dx += __shfl_xor_sync(0xffffffffu, dx, o);
                    sx += __shfl_xor_sync(0xffffffffu, sx, o);
                }
                if (tIG == 0)
                    g_W1R[row][by * 2 + warpN] = make_float4(s, qd, dx, sx);
            }
    } else {
        // w13 atoms are w3 columns: store to g_P.
        #pragma unroll
        for (int i = 0; i < 2; ++i) {
            const int r = m0 + warpM * 32 + i * 16 + gID;
            #pragma unroll
            for (int j = 0; j < 4; ++j) {
                const int cp = n0 + warpN * 48 + j * 8 + 2 * tIG;
                const int co = perm_to_orig(cp);
                *reinterpret_cast<float2*>(&g_P[r * NTOT + co]) =
                    make_float2(acc[i][j][0], acc[i][j][1]);
                *reinterpret_cast<float2*>(&g_P[(r + 8) * NTOT + co]) =
                    make_float2(acc[i][j][2], acc[i][j][3]);
            }
        }
    }
    // w2 atoms: store (all CTAs)
    #pragma unroll
    for (int i = 0; i < 2; ++i) {
        const int r = m0 + warpM * 32 + i * 16 + gID;
        #pragma unroll
        for (int j = 4; j < 6; ++j) {
            const int cp = n0 + warpN * 48 + j * 8 + 2 * tIG;
            const int co = perm_to_orig(cp);
            *reinterpret_cast<float2*>(&g_P[r * NTOT + co]) =
                make_float2(acc[i][j][0], acc[i][j][1]);
            *reinterpret_cast<float2*>(&g_P[(r + 8) * NTOT + co]) =
                make_float2(acc[i][j][2], acc[i][j][3]);
        }
    }
}

// ---------------------------------------------------------------------------
// Kernel 2: finalize, warp-per-token. Reads only w2, w3 + partials.
// ---------------------------------------------------------------------------
__global__ __launch_bounds__(128) void finalize_kernel(float* __restrict__ Y)
{
    const int warp = threadIdx.x >> 5;
    const int lane = threadIdx.x & 31;
    const int m    = blockIdx.x * 4 + warp;
    const float* p = g_P + m * NTOT;

    float4 pp = (lane < 16) ? g_W1R[m][lane] : make_float4(0.f, 0.f, 0.f, 0.f);
    #pragma unroll
    for (int o = 1; o < 32; o <<= 1) {
        pp.x += __shfl_xor_sync(0xffffffffu, pp.x, o);
        pp.y += __shfl_xor_sync(0xffffffffu, pp.y, o);
        pp.z += __shfl_xor_sync(0xffffffffu, pp.z, o);
        pp.w += __shfl_xor_sync(0xffffffffu, pp.w, o);
    }
    const float sw1 = pp.x, sw1q = pp.y, sw1x = pp.z, sx = pp.w;

    float4 v[4], c[4];
    #pragma unroll
    for (int q = 0; q < 4; ++q) {
        const int off = q * 128 + lane * 4;
        v[q] = *reinterpret_cast<const float4*>(&p[D_ + off]);       // w2
        c[q] = *reinterpret_cast<const float4*>(&p[2 * D_ + off]);   // w3
    }
    float sw3 = 0.f, sw3q = 0.f;
    #pragma unroll
    for (int q = 0; q < 4; ++q) {
        sw3  += (c[q].x + c[q].y) + (c[q].z + c[q].w);
        sw3q += (c[q].x * c[q].x + c[q].y * c[q].y)
              + (c[q].z * c[q].z + c[q].w * c[q].w);
    }
    #pragma unroll
    for (int o = 1; o < 32; o <<= 1) {
        sw3  += __shfl_xor_sync(0xffffffffu, sw3,  o);
        sw3q += __shfl_xor_sync(0xffffffffu, sw3q, o);
    }

    const float invD = 1.0f / (float)D_;
    const float mu1  = sw1 * invD;
    const float var1 = fmaxf(sw1q * invD - mu1 * mu1, 0.f);
    const float s    = sw1x - mu1 * sx;
    const float mu3  = sw3 * invD;
    const float var3 = fmaxf(sw3q * invD - mu3 * mu3, 0.f);
    const float inv3 = rsqrtf(var3 + EPS_);

    #pragma unroll
    for (int q = 0; q < 4; ++q) {
        float4 out;
        out.x = v[q].x * s * rsqrtf(v[q].x * v[q].x * var1 + EPS_)
              + (c[q].x - mu3) * inv3;
        out.y = v[q].y * s * rsqrtf(v[q].y * v[q].y * var1 + EPS_)
              + (c[q].y - mu3) * inv3;
        out.z = v[q].z * s * rsqrtf(v[q].z * v[q].z * var1 + EPS_)
              + (c[q].z - mu3) * inv3;
        out.w = v[q].w * s * rsqrtf(v[q].w * v[q].w * var1 + EPS_)
              + (c[q].w - mu3) * inv3;
        *reinterpret_cast<float4*>(&Y[m * D_ + q * 128 + lane * 4]) = out;
    }
}

// ---------------------------------------------------------------------------
extern "C" void kernel_launch(void* const* d_in, const int* in_sizes, int n_in,
                              void* d_out, int out_size)
{
    const float* X    = (const float*)d_in[0];
    const float* Win  = (const float*)d_in[1];
    const float* Wout = (const float*)d_in[2];
    const float* Wb   = (const float*)d_in[3];
    float* Y = (float*)d_out;

    cudaFuncSetAttribute(gemm3_fused,
                         cudaFuncAttributeMaxDynamicSharedMemorySize, GSMEM);

    gemm3_fused<<<dim3(MTOK / BM, NTOT / BN), 256, GSMEM>>>(X, Win, Wout, Wb);
    finalize_kernel<<<MTOK / 4, 128>>>(Y);
}

// round 15
// speedup vs baseline: 1.0209x; 1.0209x over previous
#include <cuda_runtime.h>
#include <cuda_fp16.h>
#include <cstdint>

// Problem constants
#define B_    2
#define S_    512
#define D_    512
#define MTOK  1024          // B*S tokens
#define NTOT  1536          // w1 | w2 | w3
#define EPS_  1e-5f

// Static device scratch
__device__ float  g_P[MTOK * NTOT];     // w2|w3 projections (w1 region unused)
__device__ float4 g_W1R[MTOK][16];      // per-token partials: sum,sq,dot,sx
__device__ __half g_A0[MTOK * D_];      // X hi split
__device__ __half g_A1[MTOK * D_];      // X lo split
__device__ __half g_B0[NTOT * D_];      // W hi split, PERMUTED row order
__device__ __half g_B1[512 * D_];       // W lo split, w2 rows ONLY (compact)

// Column permutation: every 48-block = [32 w13-cols][16 w2-cols].
// Original concat: w1=[0,512) w2=[512,1024) w3=[1024,1536).
__device__ __forceinline__ int perm_to_orig(int p) {
    const int b = p / 48, r = p % 48;
    if (r < 32) { const int u = b * 32 + r; return (u < 512) ? u : u + 512; }
    return 512 + b * 16 + (r - 32);
}

// ---------------------------------------------------------------------------
// Kernel 0: split fp32 -> fp16 hi/lo. B-hi full permuted; B-lo only w2 rows.
// ---------------------------------------------------------------------------
#define XFL   (MTOK * D_)              // 524288 floats in X
#define TOTG  ((MTOK + NTOT) * D_ / 8) // 163840 groups of 8

__global__ __launch_bounds__(256) void split_kernel(
    const float* __restrict__ X,
    const float* __restrict__ Win,
    const float* __restrict__ Wout,
    const float* __restrict__ Wb)
{
    const int g = blockIdx.x * 256 + threadIdx.x;
    if (g >= TOTG) return;
    const int q = g * 8;

    const float* src;
    __half *d0, *d1 = nullptr;
    if (q < XFL) {
        src = X + q;
        d0 = g_A0 + q;  d1 = g_A1 + q;
    } else {
        const int wq = q - XFL;
        const int np = wq >> 9;            // permuted row
        const int k  = wq & (D_ - 1);
        const int o  = perm_to_orig(np);   // original concat col
        src = (o < D_ ? Win + o * D_
                      : (o < 2 * D_ ? Wout + (o - D_) * D_
                                    : Wb + (o - 2 * D_) * D_)) + k;
        d0 = g_B0 + wq;
        const int r48 = np % 48;
        if (r48 >= 32)                     // w2 row -> compact lo array
            d1 = g_B1 + ((np / 48) * 16 + (r48 - 32)) * D_ + k;
    }
    const float4 v0 = reinterpret_cast<const float4*>(src)[0];
    const float4 v1 = reinterpret_cast<const float4*>(src)[1];
    float f[8] = {v0.x, v0.y, v0.z, v0.w, v1.x, v1.y, v1.z, v1.w};
    __half hi[8], lo[8];
    #pragma unroll
    for (int i = 0; i < 8; ++i) {
        hi[i] = __float2half_rn(f[i]);
        lo[i] = __float2half_rn(f[i] - __half2float(hi[i]));
    }
    uint4 sh, sl;
    sh.x = *(uint32_t*)&hi[0]; sh.y = *(uint32_t*)&hi[2];
    sh.z = *(uint32_t*)&hi[4]; sh.w = *(uint32_t*)&hi[6];
    sl.x = *(uint32_t*)&lo[0]; sl.y = *(uint32_t*)&lo[2];
    sl.z = *(uint32_t*)&lo[4]; sl.w = *(uint32_t*)&lo[6];
    *reinterpret_cast<uint4*>(d0) = sh;
    if (d1) *reinterpret_cast<uint4*>(d1) = sl;
}

// ---------------------------------------------------------------------------
// Kernel 1: GEMM (R12 config): mixed pass-count, 3-stage cp.async pipeline,
// ldmatrix fragment loads, fused w1 reduction. BM=128 BN=96 BK=32, grid 8x16.
// ---------------------------------------------------------------------------
#define BM 128
#define BN 96
#define BK 32
#define KP 40
#define A_OFF   0
#define A1_OFF  (BM * KP)                    // 5120
#define B_OFF   (2 * BM * KP)                // 10240
#define B1_OFF  (2 * BM * KP + BN * KP)      // 14080 (compact: 32 rows)
#define STAGE_H (2 * BM * KP + BN * KP + 32 * KP)  // 15360 halves
#define NSTG    3
#define GSMEM   (NSTG * STAGE_H * 2)               // 92160 B

__device__ __forceinline__ void cp16(uint32_t smem, const void* gmem) {
    asm volatile("cp.async.cg.shared.global [%0], [%1], 16;\n"
                 :: "r"(smem), "l"(gmem));
}

__device__ __forceinline__ void ldsm_x4(uint32_t* r, uint32_t addr) {
    asm volatile("ldmatrix.sync.aligned.m8n8.x4.shared.b16 {%0,%1,%2,%3}, [%4];"
        : "=r"(r[0]), "=r"(r[1]), "=r"(r[2]), "=r"(r[3]) : "r"(addr));
}

__device__ __forceinline__ void mma_f16(float* c,
    uint32_t a0, uint32_t a1, uint32_t a2, uint32_t a3,
    uint32_t b0, uint32_t b1)
{
    asm volatile(
        "mma.sync.aligned.m16n8k16.row.col.f32.f16.f16.f32 "
        "{%0,%1,%2,%3}, {%4,%5,%6,%7}, {%8,%9}, {%0,%1,%2,%3};"
        : "+f"(c[0]), "+f"(c[1]), "+f"(c[2]), "+f"(c[3])
        : "r"(a0), "r"(a1), "r"(a2), "r"(a3), "r"(b0), "r"(b1));
}

__global__ __launch_bounds__(256, 1) void gemm3_f16(const float* __restrict__ X)
{
    extern __shared__ __half sm[];

    const int tid   = threadIdx.x;
    const int lane  = tid & 31;
    const int wid   = tid >> 5;
    const int warpM = wid >> 1;         // 0..3
    const int warpN = wid & 1;          // 0..1
    const int gID   = lane >> 2;        // 0..7
    const int tIG   = lane & 3;         // 0..3
    const int m0    = blockIdx.x * BM;
    const int by    = blockIdx.y;
    const int n0    = by * BN;          // permuted col base
    const int w2b   = by * 32;          // compact B1 row base

    const uint32_t sbase = (uint32_t)__cvta_generic_to_shared(sm);

    // ldmatrix per-thread address components (within a stage, in halves)
    const int rA  = warpM * 32 + (lane & 15);
    const int cA  = (lane >> 4) * 8;
    const int tB  = lane >> 3;
    const int rBh = warpN * 48 + (tB >> 1) * 8 + (lane & 7);
    const int rBl = warpN * 16 + (tB >> 1) * 8 + (lane & 7);
    const int cB  = (tB & 1) * 8;

    float acc[2][6][4];
    #pragma unroll
    for (int i = 0; i < 2; i++)
        #pragma unroll
        for (int j = 0; j < 6; j++)
            #pragma unroll
            for (int q = 0; q < 4; q++) acc[i][j][q] = 0.f;

    auto issue = [&](int t, int stg) {
        const int k0 = t * BK;
        const uint32_t st = sbase + (uint32_t)(stg * STAGE_H) * 2u;
        #pragma unroll
        for (int it = 0; it < 2; ++it) {
            const int c = tid + it * 256;
            const int r = c >> 2, qd = c & 3;
            const uint32_t so = (uint32_t)(r * KP + qd * 8) * 2u;
            cp16(st + A_OFF * 2u + so,  g_A0 + (m0 + r) * D_ + k0 + qd * 8);
            cp16(st + A1_OFF * 2u + so, g_A1 + (m0 + r) * D_ + k0 + qd * 8);
        }
        #pragma unroll
        for (int c = tid; c < 384; c += 256) {
            const int r = c >> 2, qd = c & 3;
            cp16(st + B_OFF * 2u + (uint32_t)(r * KP + qd * 8) * 2u,
                 g_B0 + (n0 + r) * D_ + k0 + qd * 8);
        }
        if (tid < 128) {                 // B1 compact: 32 rows x 4 chunks
            const int r = tid >> 2, qd = tid & 3;
            cp16(st + B1_OFF * 2u + (uint32_t)(r * KP + qd * 8) * 2u,
                 g_B1 + (w2b + r) * D_ + k0 + qd * 8);
        }
        asm volatile("cp.async.commit_group;");
    };

    auto compute = [&](int stg) {
        const uint32_t sst = sbase + (uint32_t)(stg * STAGE_H) * 2u;
        const uint32_t aA0 = sst + (uint32_t)(A_OFF  + rA * KP + cA) * 2u;
        const uint32_t aA1 = sst + (uint32_t)(A1_OFF + rA * KP + cA) * 2u;
        const uint32_t aBh = sst + (uint32_t)(B_OFF  + rBh * KP + cB) * 2u;
        const uint32_t aBl = sst + (uint32_t)(B1_OFF + rBl * KP + cB) * 2u;
        #pragma unroll
        for (int kk = 0; kk < BK; kk += 16) {
            const uint32_t ko = (uint32_t)(kk * 2);
            uint32_t ah[2][4], al[2][4], bh[6][2], bl[2][2];
            ldsm_x4(ah[0], aA0 + ko);
            ldsm_x4(ah[1], aA0 + ko + (uint32_t)(16 * KP * 2));
            ldsm_x4(al[0], aA1 + ko);
            ldsm_x4(al[1], aA1 + ko + (uint32_t)(16 * KP * 2));
            #pragma unroll
            for (int p = 0; p < 3; ++p) {
                uint32_t r[4];
                ldsm_x4(r, aBh + ko + (uint32_t)(p * 16 * KP * 2));
                bh[2 * p][0] = r[0];  bh[2 * p][1] = r[1];
                bh[2 * p + 1][0] = r[2];  bh[2 * p + 1][1] = r[3];
            }
            {
                uint32_t r[4];
                ldsm_x4(r, aBl + ko);
                bl[0][0] = r[0];  bl[0][1] = r[1];
                bl[1][0] = r[2];  bl[1][1] = r[3];
            }
            // w2 atoms: 3-pass exact
            #pragma unroll
            for (int i = 0; i < 2; ++i)
                #pragma unroll
                for (int jj = 0; jj < 2; ++jj)
                    mma_f16(acc[i][4 + jj], ah[i][0], ah[i][1], ah[i][2], ah[i][3],
                            bl[jj][0], bl[jj][1]);
            #pragma unroll
            for (int i = 0; i < 2; ++i)
                #pragma unroll
                for (int jj = 0; jj < 2; ++jj)
                    mma_f16(acc[i][4 + jj], al[i][0], al[i][1], al[i][2], al[i][3],
                            bh[4 + jj][0], bh[4 + jj][1]);
            // all atoms: ah*bh
            #pragma unroll
            for (int i = 0; i < 2; ++i)
                #pragma unroll
                for (int j = 0; j < 6; ++j)
                    mma_f16(acc[i][j], ah[i][0], ah[i][1], ah[i][2], ah[i][3],
                            bh[j][0], bh[j][1]);
        }
    };

    constexpr int T = D_ / BK;   // 16
    issue(0, 0);
    issue(1, 1);
    #pragma unroll 1
    for (int t = 0; t < T; ++t) {
        if (t + 1 < T) asm volatile("cp.async.wait_group 1;");
        else           asm volatile("cp.async.wait_group 0;");
        __syncthreads();
        compute(t % NSTG);
        // NSTG=3: issue(t+2) writes stage (t-1)%3, finished by ALL warps
        // before this iteration's barrier -> no second __syncthreads needed.
        if (t + 2 < T) issue(t + 2, (t + 2) % NSTG);
    }

    // -------- Epilogue --------
    if (by < 8) {
        // w13 atoms are w1 columns: reduce in-register, write partials.
        const int ub = (2 * by + warpN) * 32;       // orig col base (32 cols)
        #pragma unroll
        for (int i = 0; i < 2; ++i)
            #pragma unroll
            for (int half = 0; half < 2; ++half) {
                const int row = m0 + warpM * 32 + i * 16 + half * 8 + gID;
                float s = 0.f, qd = 0.f, dx = 0.f, sx = 0.f;
                #pragma unroll
                for (int j = 0; j < 4; ++j) {
                    const float w1a = acc[i][j][half * 2 + 0];
                    const float w1b = acc[i][j][half * 2 + 1];
                    const float2 xv = *reinterpret_cast<const float2*>(
                        &X[row * D_ + ub + j * 8 + 2 * tIG]);
                    s  += w1a + w1b;
                    qd += w1a * w1a + w1b * w1b;
                    dx += w1a * xv.x + w1b * xv.y;
                    sx += xv.x + xv.y;
                }
                #pragma unroll
                for (int o = 1; o < 4; o <<= 1) {
                    s  += __shfl_xor_sync(0xffffffffu, s,  o);
                    qd += __shfl_xor_sync(0xffffffffu, qd, o);
                    dx += __shfl_xor_sync(0xffffffffu, dx, o);
                    sx += __shfl_xor_sync(0xffffffffu, sx, o);
                }
                if (tIG == 0)
                    g_W1R[row][by * 2 + warpN] = make_float4(s, qd, dx, sx);
            }
    } else {
        // w13 atoms are w3 columns: store to g_P.
        #pragma unroll
        for (int i = 0; i < 2; ++i) {
            const int r = m0 + warpM * 32 + i * 16 + gID;
            #pragma unroll
            for (int j = 0; j < 4; ++j) {
                const int cp = n0 + warpN * 48 + j * 8 + 2 * tIG;
                const int co = perm_to_orig(cp);
                *reinterpret_cast<float2*>(&g_P[r * NTOT + co]) =
                    make_float2(acc[i][j][0], acc[i][j][1]);
                *reinterpret_cast<float2*>(&g_P[(r + 8) * NTOT + co]) =
                    make_float2(acc[i][j][2], acc[i][j][3]);
            }
        }
    }
    // w2 atoms: store (all CTAs)
    #pragma unroll
    for (int i = 0; i < 2; ++i) {
        const int r = m0 + warpM * 32 + i * 16 + gID;
        #pragma unroll
        for (int j = 4; j < 6; ++j) {
            const int cp = n0 + warpN * 48 + j * 8 + 2 * tIG;
            const int co = perm_to_orig(cp);
            *reinterpret_cast<float2*>(&g_P[r * NTOT + co]) =
                make_float2(acc[i][j][0], acc[i][j][1]);
            *reinterpret_cast<float2*>(&g_P[(r + 8) * NTOT + co]) =
                make_float2(acc[i][j][2], acc[i][j][3]);
        }
    }
}

// ---------------------------------------------------------------------------
// Kernel 2: finalize, BLOCK-per-token (128 thr, 4 warps) for occupancy.
// Each thread: one float4 of w2 + one of w3. Warp 0 gathers w1 partials in
// parallel with the w3 warp reductions; one __syncthreads.
// ---------------------------------------------------------------------------
__global__ __launch_bounds__(128) void finalize_kernel(float* __restrict__ Y)
{
    __shared__ float red[2][4];
    __shared__ float4 w1s;
    const int m    = blockIdx.x;
    const int tid  = threadIdx.x;
    const int warp = tid >> 5;
    const int lane = tid & 31;
    const float* p = g_P + m * NTOT;

    const float4 v = *reinterpret_cast<const float4*>(&p[D_ + 4 * tid]);      // w2
    const float4 c = *reinterpret_cast<const float4*>(&p[2 * D_ + 4 * tid]);  // w3

    float sw3  = (c.x + c.y) + (c.z + c.w);
    float sw3q = (c.x * c.x + c.y * c.y) + (c.z * c.z + c.w * c.w);
    #pragma unroll
    for (int o = 16; o; o >>= 1) {
        sw3  += __shfl_xor_sync(0xffffffffu, sw3,  o);
        sw3q += __shfl_xor_sync(0xffffffffu, sw3q, o);
    }
    if (lane == 0) { red[0][warp] = sw3; red[1][warp] = sw3q; }

    if (warp == 0) {
        float4 pp = (lane < 16) ? g_W1R[m][lane]
                                : make_float4(0.f, 0.f, 0.f, 0.f);
        #pragma unroll
        for (int o = 1; o < 32; o <<= 1) {
            pp.x += __shfl_xor_sync(0xffffffffu, pp.x, o);
            pp.y += __shfl_xor_sync(0xffffffffu, pp.y, o);
            pp.z += __shfl_xor_sync(0xffffffffu, pp.z, o);
            pp.w += __shfl_xor_sync(0xffffffffu, pp.w, o);
        }
        if (lane == 0) w1s = pp;
    }
    __syncthreads();

    const float tw3  = (red[0][0] + red[0][1]) + (red[0][2] + red[0][3]);
    const float tw3q = (red[1][0] + red[1][1]) + (red[1][2] + red[1][3]);
    const float4 w1 = w1s;   // sum, sq, dot, sx

    const float invD = 1.0f / (float)D_;
    const float mu1  = w1.x * invD;
    const float var1 = fmaxf(w1.y * invD - mu1 * mu1, 0.f);
    const float s    = w1.z - mu1 * w1.w;
    const float mu3  = tw3 * invD;
    const float var3 = fmaxf(tw3q * invD - mu3 * mu3, 0.f);
    const float inv3 = rsqrtf(var3 + EPS_);

    float4 out;
    out.x = v.x * s * rsqrtf(v.x * v.x * var1 + EPS_) + (c.x - mu3) * inv3;
    out.y = v.y * s * rsqrtf(v.y * v.y * var1 + EPS_) + (c.y - mu3) * inv3;
    out.z = v.z * s * rsqrtf(v.z * v.z * var1 + EPS_) + (c.z - mu3) * inv3;
    out.w = v.w * s * rsqrtf(v.w * v.w * var1 + EPS_) + (c.w - mu3) * inv3;
    *reinterpret_cast<float4*>(&Y[m * D_ + 4 * tid]) = out;
}

// ---------------------------------------------------------------------------
extern "C" void kernel_launch(void* const* d_in, const int* in_sizes, int n_in,
                              void* d_out, int out_size)
{
    const float* X    = (const float*)d_in[0];
    const float* Win  = (const float*)d_in[1];
    const float* Wout = (const float*)d_in[2];
    const float* Wb   = (const float*)d_in[3];
    float* Y = (float*)d_out;

    cudaFuncSetAttribute(gemm3_f16,
                         cudaFuncAttributeMaxDynamicSharedMemorySize, GSMEM);

    split_kernel<<<(TOTG + 255) / 256, 256>>>(X, Win, Wout, Wb);
    gemm3_f16<<<dim3(MTOK / BM, NTOT / BN), 256, GSMEM>>>(X);
    finalize_kernel<<<MTOK, 128>>>(Y);
}